// round 5
// baseline (speedup 1.0000x reference)
#include <cuda_runtime.h>
#include <cuda_bf16.h>
#include <cstdint>
#include <cstddef>

#define PB 4
#define PC 512
#define PCK 64
#define PN 4096

typedef __nv_bfloat16 bf16;

// ---------------- static scratch ----------------
__device__ bf16  g_xT[(size_t)PB * PN * PC];     // [b][n][c]
__device__ bf16  g_Wkb[PCK * PC];
__device__ bf16  g_Wvb[PC * PC];
__device__ bf16  g_qkt[(size_t)PB * PN * PCK];   // [b][n][ck]
__device__ bf16  g_v[(size_t)PB * PC * PN];      // [b][c][m]
__device__ bf16  g_attb[(size_t)PB * PN * PN];   // [b][n][m]

// ---------------- helpers ----------------
static __device__ __forceinline__ uint32_t s2u(const void* p) {
    uint32_t a;
    asm("{ .reg .u64 t; cvta.to.shared.u64 t, %1; cvt.u32.u64 %0, t; }" : "=r"(a) : "l"(p));
    return a;
}
static __device__ __forceinline__ void cp16(uint32_t dst, const void* src) {
    asm volatile("cp.async.cg.shared.global [%0], [%1], 16;" :: "r"(dst), "l"(src));
}
static __device__ __forceinline__ void ldm4(uint32_t a, uint32_t* r) {
    asm volatile("ldmatrix.sync.aligned.m8n8.x4.shared.b16 {%0,%1,%2,%3}, [%4];"
                 : "=r"(r[0]), "=r"(r[1]), "=r"(r[2]), "=r"(r[3]) : "r"(a));
}
static __device__ __forceinline__ void mma16816(float* d, const uint32_t* a,
                                                uint32_t b0, uint32_t b1) {
    asm volatile(
        "mma.sync.aligned.m16n8k16.row.col.f32.bf16.bf16.f32 "
        "{%0,%1,%2,%3}, {%4,%5,%6,%7}, {%8,%9}, {%0,%1,%2,%3};"
        : "+f"(d[0]), "+f"(d[1]), "+f"(d[2]), "+f"(d[3])
        : "r"(a[0]), "r"(a[1]), "r"(a[2]), "r"(a[3]), "r"(b0), "r"(b1));
}

// load a tile of `rows` x 64 bf16 (128B/row) into swizzled smem
static __device__ __forceinline__ void load_tile(uint32_t sm, const bf16* g, int ld,
                                                 int rows, int tid) {
    for (int u = tid; u < rows * 8; u += 256) {
        int r = u >> 3, c = u & 7;
        cp16(sm + (uint32_t)(r * 128 + ((c ^ (r & 7)) << 4)), g + (size_t)r * ld + c * 8);
    }
}

// ---------------- generic bf16 warp-MMA GEMM ----------------
// D[m][n] = sum_k A[m][k]*B[n][k];  A,B K-major bf16.  M-tile 128, N-tile NTILE, BK=64.
// MODE 1: +bias[n] -> bf16. 2: +bias[m] -> bf16. 3: gamma*D + x -> fp32.
template <int NTILE, int MODE>
__global__ void __launch_bounds__(256)
tc_gemm(const bf16* __restrict__ Aall, const bf16* __restrict__ Ball,
        void* __restrict__ Call, int K, int lda, int ldb, int ldc,
        long long sA, long long sB, long long sC,
        const float* __restrict__ bias, const float* __restrict__ xres,
        const float* __restrict__ gscale) {
    constexpr int ABYT = 128 * 128;
    constexpr int BBYT = NTILE * 128;
    constexpr int STG  = ABYT + BBYT;
    constexpr int NT_W = NTILE / 4;
    constexpr int NFRag = NT_W / 8;
    extern __shared__ __align__(1024) char smem[];

    const int tid = threadIdx.x;
    const int wid = tid >> 5;
    const int lane = tid & 31;
    const int wm = wid >> 2;
    const int wn = wid & 3;
    const int bz = blockIdx.z;
    const int m0 = blockIdx.y * 128;
    const int n0 = blockIdx.x * NTILE;
    const uint32_t sbase = s2u(smem);

    const bf16* Ab = Aall + (size_t)bz * sA + (size_t)m0 * lda;
    const bf16* Bb = Ball + (size_t)bz * sB + (size_t)n0 * ldb;
    const int nK = K >> 6;

    float acc[4][NFRag][4];
#pragma unroll
    for (int i = 0; i < 4; i++)
#pragma unroll
        for (int j = 0; j < NFRag; j++)
#pragma unroll
            for (int q = 0; q < 4; q++) acc[i][j][q] = 0.f;

    const int l15 = lane & 15;
    const int swz = lane & 7;
    const int cbase = lane >> 4;

#pragma unroll
    for (int j = 0; j < 2; j++) {
        if (j < nK) {
            uint32_t s = sbase + j * STG;
            load_tile(s, Ab + j * 64, lda, 128, tid);
            load_tile(s + ABYT, Bb + j * 64, ldb, NTILE, tid);
        }
        asm volatile("cp.async.commit_group;");
    }

    for (int i = 0; i < nK; i++) {
        asm volatile("cp.async.wait_group 1;");
        __syncthreads();
        const int j = i + 2;
        if (j < nK) {
            uint32_t s = sbase + (j % 3) * STG;
            load_tile(s, Ab + j * 64, lda, 128, tid);
            load_tile(s + ABYT, Bb + j * 64, ldb, NTILE, tid);
        }
        asm volatile("cp.async.commit_group;");

        const uint32_t sA_ = sbase + (i % 3) * STG;
        const uint32_t sB_ = sA_ + ABYT;
#pragma unroll
        for (int ks = 0; ks < 4; ks++) {
            const int chunk = ks * 2 + cbase;
            uint32_t a[4][4];
#pragma unroll
            for (int mf = 0; mf < 4; mf++) {
                int row = wm * 64 + mf * 16 + l15;
                ldm4(sA_ + (uint32_t)(row * 128 + ((chunk ^ swz) << 4)), a[mf]);
            }
            uint32_t b[2 * ((NFRag + 1) / 2)][2];
#pragma unroll
            for (int np = 0; np < NFRag / 2; np++) {
                uint32_t r[4];
                int row = wn * NT_W + np * 16 + l15;
                ldm4(sB_ + (uint32_t)(row * 128 + ((chunk ^ swz) << 4)), r);
                b[2 * np][0] = r[0]; b[2 * np][1] = r[2];
                b[2 * np + 1][0] = r[1]; b[2 * np + 1][1] = r[3];
            }
#pragma unroll
            for (int mf = 0; mf < 4; mf++)
#pragma unroll
                for (int nf = 0; nf < NFRag; nf++)
                    mma16816(acc[mf][nf], a[mf], b[nf][0], b[nf][1]);
        }
    }

    const int g = lane >> 2, tg = lane & 3;
    float gv = 0.f;
    if (MODE == 3) gv = __ldg(gscale);
#pragma unroll
    for (int mf = 0; mf < 4; mf++) {
#pragma unroll
        for (int nf = 0; nf < NFRag; nf++) {
            const float* d = acc[mf][nf];
            const int col = n0 + wn * NT_W + nf * 8 + tg * 2;
            const size_t row0 = (size_t)m0 + wm * 64 + mf * 16 + g;
            const size_t row1 = row0 + 8;
            const size_t o0 = (size_t)bz * sC + row0 * ldc + col;
            const size_t o1 = (size_t)bz * sC + row1 * ldc + col;
            if (MODE == 1) {
                const float b0 = __ldg(bias + col), b1 = __ldg(bias + col + 1);
                bf16* C = (bf16*)Call;
                *(__nv_bfloat162*)(C + o0) = __floats2bfloat162_rn(d[0] + b0, d[1] + b1);
                *(__nv_bfloat162*)(C + o1) = __floats2bfloat162_rn(d[2] + b0, d[3] + b1);
            } else if (MODE == 2) {
                bf16* C = (bf16*)Call;
                const float br0 = __ldg(bias + row0), br1 = __ldg(bias + row1);
                *(__nv_bfloat162*)(C + o0) = __floats2bfloat162_rn(d[0] + br0, d[1] + br0);
                *(__nv_bfloat162*)(C + o1) = __floats2bfloat162_rn(d[2] + br1, d[3] + br1);
            } else {
                float* C = (float*)Call;
                float2 x0 = *(const float2*)(xres + o0);
                float2 x1 = *(const float2*)(xres + o1);
                *(float2*)(C + o0) = make_float2(fmaf(gv, d[0], x0.x), fmaf(gv, d[1], x0.y));
                *(float2*)(C + o1) = make_float2(fmaf(gv, d[2], x1.x), fmaf(gv, d[3], x1.y));
            }
        }
    }
}

// ---------------- fused scores + softmax -> bf16 attention ----------------
// Per CTA: 64 query rows (n), two passes over all 4096 keys (m) in tiles of 128.
// Pass 1: online (rowmax, rowsum) from register-resident S tiles.
// Pass 2: recompute S (bitwise-identical), normalize, write bf16 att[n][m].
// 8 warps: wn = wid>>1 (16-row strip), wm = wid&1 (64-col m half).
#define FA_QB   0
#define FA_KB   8192
#define FA_KSZ  16384
#define FA_STAGE (FA_KB + 3 * FA_KSZ)          // 57344
#define FA_SM   (FA_STAGE + 16384)             // 73728
#define FA_SL   (FA_SM + 512)                  // 74240
#define FA_TOT  (FA_SL + 512)                  // 74752

__global__ void __launch_bounds__(256)
fused_att(const bf16* __restrict__ qkt, bf16* __restrict__ att) {
    extern __shared__ __align__(1024) char smem[];
    const uint32_t sb = s2u(smem);
    const int tid = threadIdx.x;
    const int wid = tid >> 5;
    const int lane = tid & 31;
    const int wn = wid >> 1;
    const int wm = wid & 1;
    const int l15 = lane & 15;
    const int swz = lane & 7;
    const int cbase = lane >> 4;
    const int g = lane >> 2, tg = lane & 3;
    const int bz = blockIdx.y;
    const int n0 = blockIdx.x * 64;

    const bf16* Kb = qkt + (size_t)bz * PN * PCK;
    const bf16* Qb = Kb + (size_t)n0 * PCK;

    uint32_t aq[4][4];            // persistent q fragments (4 k-steps)
    float mrun[2] = {-1e30f, -1e30f};
    float lrun[2] = {0.f, 0.f};

    // ---- pass 1 prologue: q + ktile0 (group0), ktile1 (group1)
    load_tile(sb + FA_QB, Qb, PCK, 64, tid);
    load_tile(sb + FA_KB, Kb, PCK, 128, tid);
    asm volatile("cp.async.commit_group;");
    load_tile(sb + FA_KB + FA_KSZ, Kb + (size_t)128 * PCK, PCK, 128, tid);
    asm volatile("cp.async.commit_group;");

#pragma unroll 1
    for (int i = 0; i < 32; i++) {
        asm volatile("cp.async.wait_group 1;");
        __syncthreads();
        if (i == 0) {
#pragma unroll
            for (int ks = 0; ks < 4; ks++) {
                int row = wn * 16 + l15;
                ldm4(sb + FA_QB + (uint32_t)(row * 128 + (((ks * 2 + cbase) ^ swz) << 4)), aq[ks]);
            }
        }
        const int j = i + 2;
        if (j < 32) load_tile(sb + FA_KB + (j % 3) * FA_KSZ, Kb + (size_t)j * 128 * PCK, PCK, 128, tid);
        asm volatile("cp.async.commit_group;");

        const uint32_t ks_ = sb + FA_KB + (i % 3) * FA_KSZ;
        float acc[8][4];
#pragma unroll
        for (int t = 0; t < 8; t++)
#pragma unroll
            for (int q = 0; q < 4; q++) acc[t][q] = 0.f;
#pragma unroll
        for (int ks = 0; ks < 4; ks++) {
            const int chunk = ks * 2 + cbase;
#pragma unroll
            for (int t16 = 0; t16 < 4; t16++) {
                uint32_t r[4];
                int row = wm * 64 + t16 * 16 + l15;
                ldm4(ks_ + (uint32_t)(row * 128 + ((chunk ^ swz) << 4)), r);
                mma16816(acc[2 * t16], aq[ks], r[0], r[2]);
                mma16816(acc[2 * t16 + 1], aq[ks], r[1], r[3]);
            }
        }
        // online update (per row pair)
#pragma unroll
        for (int rp = 0; rp < 2; rp++) {
            float tm = acc[0][2 * rp];
#pragma unroll
            for (int t = 0; t < 8; t++) {
                tm = fmaxf(tm, acc[t][2 * rp]);
                tm = fmaxf(tm, acc[t][2 * rp + 1]);
            }
            tm = fmaxf(tm, __shfl_xor_sync(0xFFFFFFFFu, tm, 1));
            tm = fmaxf(tm, __shfl_xor_sync(0xFFFFFFFFu, tm, 2));
            const float mn = fmaxf(mrun[rp], tm);
            float ps = 0.f;
#pragma unroll
            for (int t = 0; t < 8; t++) {
                ps += __expf(acc[t][2 * rp] - mn);
                ps += __expf(acc[t][2 * rp + 1] - mn);
            }
            ps += __shfl_xor_sync(0xFFFFFFFFu, ps, 1);
            ps += __shfl_xor_sync(0xFFFFFFFFu, ps, 2);
            lrun[rp] = lrun[rp] * __expf(mrun[rp] - mn) + ps;
            mrun[rp] = mn;
        }
    }
    asm volatile("cp.async.wait_group 0;");
    __syncthreads();

    // ---- combine stats across the two m-half warps
    if (tg == 0) {
#pragma unroll
        for (int rp = 0; rp < 2; rp++) {
            int row = wn * 16 + g + 8 * rp;
            *(float*)(smem + FA_SM + (wm * 64 + row) * 4) = mrun[rp];
            *(float*)(smem + FA_SL + (wm * 64 + row) * 4) = lrun[rp];
        }
    }
    __syncthreads();
    float Mf[2], invl[2];
#pragma unroll
    for (int rp = 0; rp < 2; rp++) {
        int row = wn * 16 + g + 8 * rp;
        float m0v = *(float*)(smem + FA_SM + row * 4);
        float m1v = *(float*)(smem + FA_SM + (64 + row) * 4);
        float l0v = *(float*)(smem + FA_SL + row * 4);
        float l1v = *(float*)(smem + FA_SL + (64 + row) * 4);
        float M = fmaxf(m0v, m1v);
        float L = l0v * __expf(m0v - M) + l1v * __expf(m1v - M);
        Mf[rp] = M;
        invl[rp] = 1.f / L;
    }
    __syncthreads();

    // ---- pass 2: recompute, normalize, store
    load_tile(sb + FA_KB, Kb, PCK, 128, tid);
    asm volatile("cp.async.commit_group;");
    load_tile(sb + FA_KB + FA_KSZ, Kb + (size_t)128 * PCK, PCK, 128, tid);
    asm volatile("cp.async.commit_group;");

#pragma unroll 1
    for (int i = 0; i < 32; i++) {
        asm volatile("cp.async.wait_group 1;");
        __syncthreads();
        const int j = i + 2;
        if (j < 32) load_tile(sb + FA_KB + (j % 3) * FA_KSZ, Kb + (size_t)j * 128 * PCK, PCK, 128, tid);
        asm volatile("cp.async.commit_group;");

        const uint32_t ks_ = sb + FA_KB + (i % 3) * FA_KSZ;
        float acc[8][4];
#pragma unroll
        for (int t = 0; t < 8; t++)
#pragma unroll
            for (int q = 0; q < 4; q++) acc[t][q] = 0.f;
#pragma unroll
        for (int ks = 0; ks < 4; ks++) {
            const int chunk = ks * 2 + cbase;
#pragma unroll
            for (int t16 = 0; t16 < 4; t16++) {
                uint32_t r[4];
                int row = wm * 64 + t16 * 16 + l15;
                ldm4(ks_ + (uint32_t)(row * 128 + ((chunk ^ swz) << 4)), r);
                mma16816(acc[2 * t16], aq[ks], r[0], r[2]);
                mma16816(acc[2 * t16 + 1], aq[ks], r[1], r[3]);
            }
        }
        // normalize -> bf16 -> staged store
#pragma unroll
        for (int t = 0; t < 8; t++) {
#pragma unroll
            for (int rp = 0; rp < 2; rp++) {
                float e0 = __expf(acc[t][2 * rp] - Mf[rp]) * invl[rp];
                float e1 = __expf(acc[t][2 * rp + 1] - Mf[rp]) * invl[rp];
                __nv_bfloat162 h2 = __floats2bfloat162_rn(e0, e1);
                int row = wn * 16 + g + 8 * rp;
                int unit = wm * 8 + t;
                int up = unit ^ (row & 7);
                *(uint32_t*)(smem + FA_STAGE + row * 256 + up * 16 + tg * 4) =
                    *(uint32_t*)&h2;
            }
        }
        __syncthreads();
        {
            const int r = tid >> 2;
            const int ub = (tid & 3) * 4;
            bf16* orow = att + ((size_t)bz << 24) + (size_t)(n0 + r) * PN + i * 128;
#pragma unroll
            for (int ii = 0; ii < 4; ii++) {
                int u = ub + ii;
                int up = u ^ (r & 7);
                uint4 vv = *(uint4*)(smem + FA_STAGE + r * 256 + up * 16);
                *(uint4*)(orow + u * 8) = vv;
            }
        }
        __syncthreads();
    }
    asm volatile("cp.async.wait_group 0;" ::: "memory");
}

// ---------------- prep kernels ----------------
__global__ void __launch_bounds__(256) xT_kernel(const float* __restrict__ x,
                                                 bf16* __restrict__ xt) {
    __shared__ float tile[32][33];
    const int b = blockIdx.z;
    const int n0 = blockIdx.x * 32, c0 = blockIdx.y * 32;
    const int tx = threadIdx.x, ty = threadIdx.y;
    const float* xb = x + (size_t)b * PC * PN;
#pragma unroll
    for (int k = 0; k < 4; k++) {
        int c = c0 + ty + k * 8;
        tile[ty + k * 8][tx] = xb[(size_t)c * PN + n0 + tx];
    }
    __syncthreads();
    bf16* ob = xt + (size_t)b * PN * PC;
#pragma unroll
    for (int k = 0; k < 4; k++) {
        int n = n0 + ty + k * 8;
        ob[(size_t)n * PC + c0 + tx] = __float2bfloat16(tile[tx][ty + k * 8]);
    }
}

__global__ void cvt_kernel(const float* __restrict__ in, bf16* __restrict__ out, int n) {
    int i = blockIdx.x * 256 + threadIdx.x;
    if (i < n) out[i] = __float2bfloat16(in[i]);
}

// ---------------- launch ----------------
extern "C" void kernel_launch(void* const* d_in, const int* in_sizes, int n_in,
                              void* d_out, int out_size) {
    const float* x     = (const float*)d_in[0];
    const float* Wk    = (const float*)d_in[1];
    const float* bk    = (const float*)d_in[2];
    const float* Wv    = (const float*)d_in[3];
    const float* bv    = (const float*)d_in[4];
    const float* gamma = (const float*)d_in[5];
    float* out = (float*)d_out;

    bf16 *p_xT, *p_Wkb, *p_Wvb, *p_qkt, *p_v, *p_attb;
    cudaGetSymbolAddress((void**)&p_xT,   g_xT);
    cudaGetSymbolAddress((void**)&p_Wkb,  g_Wkb);
    cudaGetSymbolAddress((void**)&p_Wvb,  g_Wvb);
    cudaGetSymbolAddress((void**)&p_qkt,  g_qkt);
    cudaGetSymbolAddress((void**)&p_v,    g_v);
    cudaGetSymbolAddress((void**)&p_attb, g_attb);

    const int SM64  = 3 * (128 + 64) * 128;    // 73728
    const int SM128 = 3 * (128 + 128) * 128;   // 98304
    cudaFuncSetAttribute(tc_gemm<64, 1>,  cudaFuncAttributeMaxDynamicSharedMemorySize, SM64);
    cudaFuncSetAttribute(tc_gemm<128, 2>, cudaFuncAttributeMaxDynamicSharedMemorySize, SM128);
    cudaFuncSetAttribute(tc_gemm<128, 3>, cudaFuncAttributeMaxDynamicSharedMemorySize, SM128);
    cudaFuncSetAttribute(fused_att, cudaFuncAttributeMaxDynamicSharedMemorySize, FA_TOT);

    // prep
    cvt_kernel<<<(PCK * PC + 255) / 256, 256>>>(Wk, p_Wkb, PCK * PC);
    cvt_kernel<<<(PC * PC + 255) / 256, 256>>>(Wv, p_Wvb, PC * PC);
    xT_kernel<<<dim3(PN / 32, PC / 32, PB), dim3(32, 8)>>>(x, p_xT);

    // qkt[b][n][o] = xT[n][:]·Wk[o][:] + bk[o]      (M=4096, N=64, K=512)
    tc_gemm<64, 1><<<dim3(1, PN / 128, PB), 256, SM64>>>(
        p_xT, p_Wkb, p_qkt, PC, PC, PC, PCK,
        (long long)PN * PC, 0LL, (long long)PN * PCK, bk, nullptr, nullptr);

    // v[b][c][n] = Wv[c][:]·xT[n][:] + bv[c]        (M=512, N=4096, K=512)
    tc_gemm<128, 2><<<dim3(PN / 128, PC / 128, PB), 256, SM128>>>(
        p_Wvb, p_xT, p_v, PC, PC, PC, PN,
        0LL, (long long)PN * PC, (long long)PC * PN, bv, nullptr, nullptr);

    // fused scores + softmax -> att bf16
    fused_att<<<dim3(PN / 64, PB), 256, FA_TOT>>>(p_qkt, p_attb);

    // out[b][c][n] = gamma * (v[c][:]·att[n][:]) + x[b][c][n]   (M=512, N=4096, K=4096)
    tc_gemm<128, 3><<<dim3(PN / 128, PC / 128, PB), 256, SM128>>>(
        p_v, p_attb, out, PN, PN, PN, PN,
        (long long)PC * PN, (long long)PN * PN, (long long)PC * PN,
        nullptr, x, gamma);
}